// round 1
// baseline (speedup 1.0000x reference)
#include <cuda_runtime.h>
#include <math.h>

// ---------------- scratch (static device globals; no allocation) ----------
// Q, K, V, attn_out : each [4096, 2048] fp32 = 32 MB  -> 128 MB total
__device__ float g_Q[4096 * 2048];
__device__ float g_K[4096 * 2048];
__device__ float g_V[4096 * 2048];
__device__ float g_A[4096 * 2048];

// ---------------------------------------------------------------------------
// SGEMM  C[M,N] = A[M,K] * B[N,K]^T   (both row-major, contraction over cols)
// BM=BN=128, BK=8, 256 threads, 8x8 microtile, register prefetch.
// Requires: lda = ldb = K, ldc = N, all dims multiples of tile sizes.
// ---------------------------------------------------------------------------
__global__ void __launch_bounds__(256) gemm_nt(const float* __restrict__ A,
                                               const float* __restrict__ B,
                                               float* __restrict__ C,
                                               int M, int N, int K) {
    __shared__ float As[8][128];
    __shared__ float Bs[8][128];

    const int tid = threadIdx.x;
    const int tx = tid & 15;
    const int ty = tid >> 4;
    const int m0 = blockIdx.y << 7;
    const int n0 = blockIdx.x << 7;

    const int lrow = tid >> 1;          // 0..127
    const int lk   = (tid & 1) << 2;    // 0 or 4

    const float* Ap = A + (size_t)(m0 + lrow) * K + lk;
    const float* Bp = B + (size_t)(n0 + lrow) * K + lk;

    float acc[8][8];
#pragma unroll
    for (int i = 0; i < 8; i++)
#pragma unroll
        for (int j = 0; j < 8; j++) acc[i][j] = 0.f;

    float4 av = *(const float4*)Ap;
    float4 bv = *(const float4*)Bp;

    for (int kk = 0; kk < K; kk += 8) {
        As[lk + 0][lrow] = av.x; As[lk + 1][lrow] = av.y;
        As[lk + 2][lrow] = av.z; As[lk + 3][lrow] = av.w;
        Bs[lk + 0][lrow] = bv.x; Bs[lk + 1][lrow] = bv.y;
        Bs[lk + 2][lrow] = bv.z; Bs[lk + 3][lrow] = bv.w;
        __syncthreads();

        if (kk + 8 < K) {                       // prefetch next slab
            av = *(const float4*)(Ap + kk + 8);
            bv = *(const float4*)(Bp + kk + 8);
        }

#pragma unroll
        for (int k = 0; k < 8; k++) {
            float ar[8], br[8];
            *(float4*)(ar)     = *(const float4*)&As[k][(ty << 2)];
            *(float4*)(ar + 4) = *(const float4*)&As[k][(ty << 2) + 64];
            *(float4*)(br)     = *(const float4*)&Bs[k][(tx << 2)];
            *(float4*)(br + 4) = *(const float4*)&Bs[k][(tx << 2) + 64];
#pragma unroll
            for (int i = 0; i < 8; i++)
#pragma unroll
                for (int j = 0; j < 8; j++)
                    acc[i][j] += ar[i] * br[j];
        }
        __syncthreads();
    }

#pragma unroll
    for (int i = 0; i < 8; i++) {
        int mi = (i < 4) ? ((ty << 2) + i) : (64 + (ty << 2) + (i - 4));
        size_t base = (size_t)(m0 + mi) * N + n0;
        float4 c0 = make_float4(acc[i][0], acc[i][1], acc[i][2], acc[i][3]);
        float4 c1 = make_float4(acc[i][4], acc[i][5], acc[i][6], acc[i][7]);
        *(float4*)&C[base + (tx << 2)]      = c0;
        *(float4*)&C[base + 64 + (tx << 2)] = c1;
    }
}

// ---------------------------------------------------------------------------
// Per-(token,head) RMSNorm over 128 contiguous elements, in place.
// One warp per row; rows = S*H = 65536.
// ---------------------------------------------------------------------------
__global__ void __launch_bounds__(256) rmsnorm_rows(float* __restrict__ X,
                                                    const float* __restrict__ w,
                                                    int nrows) {
    int warp = (blockIdx.x * blockDim.x + threadIdx.x) >> 5;
    int lane = threadIdx.x & 31;
    if (warp >= nrows) return;

    float4 v = *(const float4*)&X[(size_t)warp * 128 + (lane << 2)];
    float ss = v.x * v.x + v.y * v.y + v.z * v.z + v.w * v.w;
#pragma unroll
    for (int off = 16; off > 0; off >>= 1)
        ss += __shfl_xor_sync(0xffffffffu, ss, off);

    float inv = rsqrtf(ss * (1.0f / 128.0f) + 1e-6f);
    float4 wv = *(const float4*)&w[lane << 2];
    v.x *= inv * wv.x; v.y *= inv * wv.y;
    v.z *= inv * wv.z; v.w *= inv * wv.w;
    *(float4*)&X[(size_t)warp * 128 + (lane << 2)] = v;
}

// ---------------------------------------------------------------------------
// Flash attention, fp32. 64 queries x 64 keys per inner tile, Dh=128.
// Block = 256 threads (16x16), thread microtile: S 4x4, O 4x8.
// Q/K in smem transposed [d][m] with pad 65 (odd stride -> low bank conflict).
// Online softmax. Grid: (S/64, H).
// Layout of Q/K/V/O: [S, 2048] row-major, head h occupies cols [h*128, h*128+128).
// ---------------------------------------------------------------------------
#define FA_SP 65
#define FA_SMEM ((128 * FA_SP * 2 + 64 * 128 + 64 * 64) * 4)   // 115712 bytes

__global__ void __launch_bounds__(256) flash_attn(const float* __restrict__ Qg,
                                                  const float* __restrict__ Kg,
                                                  const float* __restrict__ Vg,
                                                  float* __restrict__ Og) {
    extern __shared__ float sm[];
    float* Qs = sm;                    // [128][FA_SP]
    float* Ks = Qs + 128 * FA_SP;      // [128][FA_SP]
    float* Vs = Ks + 128 * FA_SP;      // [64][128]
    float* Ps = Vs + 64 * 128;         // [64][64]

    const int tid = threadIdx.x;
    const int tx = tid & 15;
    const int ty = tid >> 4;
    const int h  = blockIdx.y;
    const int m0 = blockIdx.x << 6;
    const int hoff = h << 7;
    const float scale = 0.08838834764831845f;   // 1/sqrt(128)

    // load Q tile transposed (scale folded in)
#pragma unroll
    for (int j = 0; j < 8; j++) {
        int f = tid + 256 * j;
        int r = f >> 5;
        int c = (f & 31) << 2;
        float4 v = *(const float4*)&Qg[(size_t)(m0 + r) * 2048 + hoff + c];
        Qs[(c + 0) * FA_SP + r] = v.x * scale;
        Qs[(c + 1) * FA_SP + r] = v.y * scale;
        Qs[(c + 2) * FA_SP + r] = v.z * scale;
        Qs[(c + 3) * FA_SP + r] = v.w * scale;
    }

    float mrow[4] = {-1e30f, -1e30f, -1e30f, -1e30f};
    float lrow[4] = {0.f, 0.f, 0.f, 0.f};
    float o[4][8];
#pragma unroll
    for (int i = 0; i < 4; i++)
#pragma unroll
        for (int j = 0; j < 8; j++) o[i][j] = 0.f;

    for (int kt = 0; kt < 4096; kt += 64) {
        // load K tile (transposed) and V tile (natural)
#pragma unroll
        for (int j = 0; j < 8; j++) {
            int f = tid + 256 * j;
            int r = f >> 5;
            int c = (f & 31) << 2;
            float4 kv = *(const float4*)&Kg[(size_t)(kt + r) * 2048 + hoff + c];
            Ks[(c + 0) * FA_SP + r] = kv.x;
            Ks[(c + 1) * FA_SP + r] = kv.y;
            Ks[(c + 2) * FA_SP + r] = kv.z;
            Ks[(c + 3) * FA_SP + r] = kv.w;
            float4 vv = *(const float4*)&Vg[(size_t)(kt + r) * 2048 + hoff + c];
            *(float4*)&Vs[r * 128 + c] = vv;
        }
        __syncthreads();

        // S = Q K^T  (4x4 per thread)
        float s[4][4];
#pragma unroll
        for (int i = 0; i < 4; i++)
#pragma unroll
            for (int j = 0; j < 4; j++) s[i][j] = 0.f;

#pragma unroll 4
        for (int d = 0; d < 128; d++) {
            float q0 = Qs[d * FA_SP + (ty << 2) + 0];
            float q1 = Qs[d * FA_SP + (ty << 2) + 1];
            float q2 = Qs[d * FA_SP + (ty << 2) + 2];
            float q3 = Qs[d * FA_SP + (ty << 2) + 3];
            float k0 = Ks[d * FA_SP + (tx << 2) + 0];
            float k1 = Ks[d * FA_SP + (tx << 2) + 1];
            float k2 = Ks[d * FA_SP + (tx << 2) + 2];
            float k3 = Ks[d * FA_SP + (tx << 2) + 3];
            s[0][0] += q0 * k0; s[0][1] += q0 * k1; s[0][2] += q0 * k2; s[0][3] += q0 * k3;
            s[1][0] += q1 * k0; s[1][1] += q1 * k1; s[1][2] += q1 * k2; s[1][3] += q1 * k3;
            s[2][0] += q2 * k0; s[2][1] += q2 * k1; s[2][2] += q2 * k2; s[2][3] += q2 * k3;
            s[3][0] += q3 * k0; s[3][1] += q3 * k1; s[3][2] += q3 * k2; s[3][3] += q3 * k3;
        }

        // online softmax (row reductions over tx = lane bits 0..3)
#pragma unroll
        for (int i = 0; i < 4; i++) {
            float mx = fmaxf(fmaxf(s[i][0], s[i][1]), fmaxf(s[i][2], s[i][3]));
#pragma unroll
            for (int off = 1; off < 16; off <<= 1)
                mx = fmaxf(mx, __shfl_xor_sync(0xffffffffu, mx, off));
            float mn = fmaxf(mrow[i], mx);
            float corr = __expf(mrow[i] - mn);
            float rs = 0.f;
#pragma unroll
            for (int j = 0; j < 4; j++) {
                s[i][j] = __expf(s[i][j] - mn);
                rs += s[i][j];
            }
#pragma unroll
            for (int off = 1; off < 16; off <<= 1)
                rs += __shfl_xor_sync(0xffffffffu, rs, off);
            lrow[i] = lrow[i] * corr + rs;
            mrow[i] = mn;
#pragma unroll
            for (int jj = 0; jj < 8; jj++) o[i][jj] *= corr;
            *(float4*)&Ps[((ty << 2) + i) * 64 + (tx << 2)] =
                make_float4(s[i][0], s[i][1], s[i][2], s[i][3]);
        }
        __syncthreads();

        // O += P * V  (4x8 per thread)
#pragma unroll 2
        for (int n = 0; n < 64; n++) {
            float4 v0 = *(const float4*)&Vs[n * 128 + (tx << 2)];
            float4 v1 = *(const float4*)&Vs[n * 128 + 64 + (tx << 2)];
#pragma unroll
            for (int i = 0; i < 4; i++) {
                float p = Ps[((ty << 2) + i) * 64 + n];
                o[i][0] += p * v0.x; o[i][1] += p * v0.y;
                o[i][2] += p * v0.z; o[i][3] += p * v0.w;
                o[i][4] += p * v1.x; o[i][5] += p * v1.y;
                o[i][6] += p * v1.z; o[i][7] += p * v1.w;
            }
        }
        __syncthreads();
    }

    // epilogue
#pragma unroll
    for (int i = 0; i < 4; i++) {
        float inv = 1.0f / lrow[i];
        size_t base = (size_t)(m0 + (ty << 2) + i) * 2048 + hoff;
        *(float4*)&Og[base + (tx << 2)] =
            make_float4(o[i][0] * inv, o[i][1] * inv, o[i][2] * inv, o[i][3] * inv);
        *(float4*)&Og[base + 64 + (tx << 2)] =
            make_float4(o[i][4] * inv, o[i][5] * inv, o[i][6] * inv, o[i][7] * inv);
    }
}

// ---------------------------------------------------------------------------
// Launch
// ---------------------------------------------------------------------------
extern "C" void kernel_launch(void* const* d_in, const int* in_sizes, int n_in,
                              void* d_out, int out_size) {
    const float* x  = (const float*)d_in[0];
    const float* wq = (const float*)d_in[1];
    const float* wk = (const float*)d_in[2];
    const float* wv = (const float*)d_in[3];
    const float* wo = (const float*)d_in[4];
    const float* qn = (const float*)d_in[5];
    const float* kn = (const float*)d_in[6];
    float* out = (float*)d_out;

    void *pq, *pk, *pv, *pa;
    cudaGetSymbolAddress(&pq, g_Q);
    cudaGetSymbolAddress(&pk, g_K);
    cudaGetSymbolAddress(&pv, g_V);
    cudaGetSymbolAddress(&pa, g_A);
    float* Q = (float*)pq;
    float* K = (float*)pk;
    float* V = (float*)pv;
    float* A = (float*)pa;

    cudaFuncSetAttribute(flash_attn, cudaFuncAttributeMaxDynamicSharedMemorySize,
                         FA_SMEM);

    const int M = 4096, D = 2048;
    dim3 gproj(D / 128, M / 128);   // (16, 32)

    gemm_nt<<<gproj, 256>>>(x, wq, Q, M, D, D);
    gemm_nt<<<gproj, 256>>>(x, wk, K, M, D, D);
    gemm_nt<<<gproj, 256>>>(x, wv, V, M, D, D);

    int nrows = M * 16;             // 65536 (token,head) rows of 128
    rmsnorm_rows<<<nrows / 8, 256>>>(Q, qn, nrows);
    rmsnorm_rows<<<nrows / 8, 256>>>(K, kn, nrows);

    flash_attn<<<dim3(M / 64, 16), 256, FA_SMEM>>>(Q, K, V, A);

    gemm_nt<<<gproj, 256>>>(A, wo, out, M, D, D);
}

// round 3
// speedup vs baseline: 1.2105x; 1.2105x over previous
#include <cuda_runtime.h>
#include <cuda_bf16.h>
#include <cstdint>
#include <math.h>

// ---------------- scratch (static device globals; no allocation) ----------
__device__ float g_Q[4096 * 2048];
__device__ float g_K[4096 * 2048];
__device__ float g_V[4096 * 2048];
__device__ float g_A[4096 * 2048];
__device__ __nv_bfloat16 g_Xhi[4096 * 2048];
__device__ __nv_bfloat16 g_Xlo[4096 * 2048];
__device__ __nv_bfloat16 g_Whi[2048 * 2048];
__device__ __nv_bfloat16 g_Wlo[2048 * 2048];

// ======================= portable PTX helpers (sm_80+) =====================
__device__ __forceinline__ uint32_t smem_u32(const void* p) {
    uint32_t a;
    asm("{ .reg .u64 t; cvta.to.shared.u64 t, %1; cvt.u32.u64 %0, t; }"
        : "=r"(a) : "l"(p));
    return a;
}
#define CP_ASYNC16(dst, src) \
    asm volatile("cp.async.cg.shared.global [%0], [%1], 16;" \
                 :: "r"(dst), "l"(src))
#define CP_COMMIT() asm volatile("cp.async.commit_group;")
#define CP_WAIT1()  asm volatile("cp.async.wait_group 1;")
#define CP_WAIT0()  asm volatile("cp.async.wait_group 0;")
#define LDSM_X4(r, addr) \
    asm volatile("ldmatrix.sync.aligned.m8n8.x4.shared.b16 {%0,%1,%2,%3}, [%4];" \
                 : "=r"((r)[0]), "=r"((r)[1]), "=r"((r)[2]), "=r"((r)[3]) \
                 : "r"(addr))
#define MMA16816(d, a, b0, b1) \
    asm volatile("mma.sync.aligned.m16n8k16.row.col.f32.bf16.bf16.f32 " \
                 "{%0,%1,%2,%3}, {%4,%5,%6,%7}, {%8,%9}, {%0,%1,%2,%3};" \
                 : "+f"((d)[0]), "+f"((d)[1]), "+f"((d)[2]), "+f"((d)[3]) \
                 : "r"((a)[0]), "r"((a)[1]), "r"((a)[2]), "r"((a)[3]), \
                   "r"(b0), "r"(b1))

// ---------------------------------------------------------------------------
// split fp32 -> bf16 hi + bf16 lo
// ---------------------------------------------------------------------------
__global__ void __launch_bounds__(256) split_bf16(const float* __restrict__ in,
                                                  __nv_bfloat16* __restrict__ hi,
                                                  __nv_bfloat16* __restrict__ lo,
                                                  int n4) {
    int i = blockIdx.x * blockDim.x + threadIdx.x;
    if (i >= n4) return;
    float4 v = ((const float4*)in)[i];
    union { __nv_bfloat16 b[4]; uint2 u; } H, L;
    H.b[0] = __float2bfloat16(v.x);
    H.b[1] = __float2bfloat16(v.y);
    H.b[2] = __float2bfloat16(v.z);
    H.b[3] = __float2bfloat16(v.w);
    L.b[0] = __float2bfloat16(v.x - __bfloat162float(H.b[0]));
    L.b[1] = __float2bfloat16(v.y - __bfloat162float(H.b[1]));
    L.b[2] = __float2bfloat16(v.z - __bfloat162float(H.b[2]));
    L.b[3] = __float2bfloat16(v.w - __bfloat162float(H.b[3]));
    ((uint2*)hi)[i] = H.u;
    ((uint2*)lo)[i] = L.u;
}

// ---------------------------------------------------------------------------
// mma.sync split-bf16 GEMM: C[M,N] = (Ahi+Alo)[M,K] * (Bhi+Blo)[N,K]^T
// CTA 128x128, K chunk 64 bf16 (128B rows, XOR-swizzled), cp.async double
// buffer, 8 warps (warp tile 64x32), 3 accumulation passes for precision.
// ---------------------------------------------------------------------------
#define GM_STAGE 32768              // A(16KB) + B(16KB)
#define GM_SMEM  (2 * GM_STAGE)

__global__ void __launch_bounds__(256, 2) gemm_mma(
    const __nv_bfloat16* __restrict__ Ahi, const __nv_bfloat16* __restrict__ Alo,
    const __nv_bfloat16* __restrict__ Bhi, const __nv_bfloat16* __restrict__ Blo,
    float* __restrict__ C, int M, int N, int K) {
    extern __shared__ char smem[];
    const uint32_t sbase = smem_u32(smem);
    const int tid = threadIdx.x;
    const int lane = tid & 31;
    const int wid = tid >> 5;
    const int m0 = blockIdx.y << 7;
    const int n0 = blockIdx.x << 7;
    const int wm = (wid & 1) << 6;       // warp m offset (0/64)
    const int wn = (wid >> 1) << 5;      // warp n offset (0/32/64/96)

    const __nv_bfloat16* PA[3] = {Ahi, Alo, Ahi};
    const __nv_bfloat16* PB[3] = {Bhi, Bhi, Blo};

    float acc[4][4][4];
#pragma unroll
    for (int mi = 0; mi < 4; mi++)
#pragma unroll
        for (int ni = 0; ni < 4; ni++)
#pragma unroll
            for (int q = 0; q < 4; q++) acc[mi][ni][q] = 0.f;

    // loader coords: 2 threads per 128B row, 4x16B chunks each
    const int lr = tid >> 1;             // 0..127
    const int lc0 = (tid & 1) << 2;      // 0 or 4

    const int NITER = 3 * (K >> 6);      // 96 for K=2048

    // --- issue stage ---
#define GM_ISSUE(it, buf) do {                                                 \
    int _p = (it) / (K >> 6);                                                  \
    int _kk = ((it) % (K >> 6)) << 6;                                          \
    const __nv_bfloat16* _Ag = PA[_p] + (size_t)(m0 + lr) * K + _kk;           \
    const __nv_bfloat16* _Bg = PB[_p] + (size_t)(n0 + lr) * K + _kk;           \
    uint32_t _rowA = sbase + (buf) * GM_STAGE + lr * 128;                      \
    uint32_t _rowB = _rowA + 16384;                                            \
    _Pragma("unroll")                                                          \
    for (int _j = 0; _j < 4; _j++) {                                           \
        int _c = lc0 + _j;                                                     \
        uint32_t _sw = (uint32_t)((_c ^ (lr & 7)) << 4);                       \
        CP_ASYNC16(_rowA + _sw, _Ag + _c * 8);                                 \
        CP_ASYNC16(_rowB + _sw, _Bg + _c * 8);                                 \
    }                                                                          \
} while (0)

    GM_ISSUE(0, 0);
    CP_COMMIT();

    for (int it = 0; it < NITER; it++) {
        const int buf = it & 1;
        if (it + 1 < NITER) {
            GM_ISSUE(it + 1, buf ^ 1);
            CP_COMMIT();
            CP_WAIT1();
        } else {
            CP_WAIT0();
        }
        __syncthreads();

        const uint32_t sA = sbase + buf * GM_STAGE;
        const uint32_t sB = sA + 16384;

#pragma unroll
        for (int ks = 0; ks < 4; ks++) {
            uint32_t a[4][4], b[2][4];
#pragma unroll
            for (int mi = 0; mi < 4; mi++) {
                int row = wm + mi * 16 + (lane & 15);
                int kb = ks * 32 + ((lane >> 4) << 4);
                uint32_t addr = sA + row * 128 + (kb ^ ((row & 7) << 4));
                LDSM_X4(a[mi], addr);
            }
#pragma unroll
            for (int pr = 0; pr < 2; pr++) {
                int row = wn + pr * 16 + (lane & 7) + (((lane >> 4) & 1) << 3);
                int kb = ks * 32 + (((lane >> 3) & 1) << 4);
                uint32_t addr = sB + row * 128 + (kb ^ ((row & 7) << 4));
                LDSM_X4(b[pr], addr);
            }
#pragma unroll
            for (int mi = 0; mi < 4; mi++)
#pragma unroll
                for (int ni = 0; ni < 4; ni++) {
                    uint32_t b0 = b[ni >> 1][(ni & 1) << 1];
                    uint32_t b1 = b[ni >> 1][((ni & 1) << 1) + 1];
                    MMA16816(acc[mi][ni], a[mi], b0, b1);
                }
        }
        __syncthreads();
    }

    // epilogue
#pragma unroll
    for (int mi = 0; mi < 4; mi++) {
        int r0 = m0 + wm + mi * 16 + (lane >> 2);
#pragma unroll
        for (int ni = 0; ni < 4; ni++) {
            int cc = n0 + wn + ni * 8 + ((lane & 3) << 1);
            float2 v0 = make_float2(acc[mi][ni][0], acc[mi][ni][1]);
            float2 v1 = make_float2(acc[mi][ni][2], acc[mi][ni][3]);
            *(float2*)&C[(size_t)r0 * N + cc] = v0;
            *(float2*)&C[(size_t)(r0 + 8) * N + cc] = v1;
        }
    }
}

// ---------------------------------------------------------------------------
// Per-(token,head) RMSNorm over 128 contiguous elements, in place.
// ---------------------------------------------------------------------------
__global__ void __launch_bounds__(256) rmsnorm_rows(float* __restrict__ X,
                                                    const float* __restrict__ w,
                                                    int nrows) {
    int warp = (blockIdx.x * blockDim.x + threadIdx.x) >> 5;
    int lane = threadIdx.x & 31;
    if (warp >= nrows) return;

    float4 v = *(const float4*)&X[(size_t)warp * 128 + (lane << 2)];
    float ss = v.x * v.x + v.y * v.y + v.z * v.z + v.w * v.w;
#pragma unroll
    for (int off = 16; off > 0; off >>= 1)
        ss += __shfl_xor_sync(0xffffffffu, ss, off);

    float inv = rsqrtf(ss * (1.0f / 128.0f) + 1e-6f);
    float4 wv = *(const float4*)&w[lane << 2];
    v.x *= inv * wv.x; v.y *= inv * wv.y;
    v.z *= inv * wv.z; v.w *= inv * wv.w;
    *(float4*)&X[(size_t)warp * 128 + (lane << 2)] = v;
}

// ---------------------------------------------------------------------------
// Flash attention, fp32 (unchanged; round-4 target for mma.sync conversion).
// ---------------------------------------------------------------------------
#define FA_SP 65
#define FA_SMEM ((128 * FA_SP * 2 + 64 * 128 + 64 * 64) * 4)

__global__ void __launch_bounds__(256) flash_attn(const float* __restrict__ Qg,
                                                  const float* __restrict__ Kg,
                                                  const float* __restrict__ Vg,
                                                  float* __restrict__ Og) {
    extern __shared__ float sm[];
    float* Qs = sm;
    float* Ks = Qs + 128 * FA_SP;
    float* Vs = Ks + 128 * FA_SP;
    float* Ps = Vs + 64 * 128;

    const int tid = threadIdx.x;
    const int tx = tid & 15;
    const int ty = tid >> 4;
    const int h  = blockIdx.y;
    const int m0 = blockIdx.x << 6;
    const int hoff = h << 7;
    const float scale = 0.08838834764831845f;

#pragma unroll
    for (int j = 0; j < 8; j++) {
        int f = tid + 256 * j;
        int r = f >> 5;
        int c = (f & 31) << 2;
        float4 v = *(const float4*)&Qg[(size_t)(m0 + r) * 2048 + hoff + c];
        Qs[(c + 0) * FA_SP + r] = v.x * scale;
        Qs[(c + 1) * FA_SP + r] = v.y * scale;
        Qs[(c + 2) * FA_SP + r] = v.z * scale;
        Qs[(c + 3) * FA_SP + r] = v.w * scale;
    }

    float mrow[4] = {-1e30f, -1e30f, -1e30f, -1e30f};
    float lrow[4] = {0.f, 0.f, 0.f, 0.f};
    float o[4][8];
#pragma unroll
    for (int i = 0; i < 4; i++)
#pragma unroll
        for (int j = 0; j < 8; j++) o[i][j] = 0.f;

    for (int kt = 0; kt < 4096; kt += 64) {
#pragma unroll
        for (int j = 0; j < 8; j++) {
            int f = tid + 256 * j;
            int r = f >> 5;
            int c = (f & 31) << 2;
            float4 kv = *(const float4*)&Kg[(size_t)(kt + r) * 2048 + hoff + c];
            Ks[(c + 0) * FA_SP + r] = kv.x;
            Ks[(c + 1) * FA_SP + r] = kv.y;
            Ks[(c + 2) * FA_SP + r] = kv.z;
            Ks[(c + 3) * FA_SP + r] = kv.w;
            float4 vv = *(const float4*)&Vg[(size_t)(kt + r) * 2048 + hoff + c];
            *(float4*)&Vs[r * 128 + c] = vv;
        }
        __syncthreads();

        float s[4][4];
#pragma unroll
        for (int i = 0; i < 4; i++)
#pragma unroll
            for (int j = 0; j < 4; j++) s[i][j] = 0.f;

#pragma unroll 4
        for (int d = 0; d < 128; d++) {
            float q0 = Qs[d * FA_SP + (ty << 2) + 0];
            float q1 = Qs[d * FA_SP + (ty << 2) + 1];
            float q2 = Qs[d * FA_SP + (ty << 2) + 2];
            float q3 = Qs[d * FA_SP + (ty << 2) + 3];
            float k0 = Ks[d * FA_SP + (tx << 2) + 0];
            float k1 = Ks[d * FA_SP + (tx << 2) + 1];
            float k2 = Ks[d * FA_SP + (tx << 2) + 2];
            float k3 = Ks[d * FA_SP + (tx << 2) + 3];
            s[0][0] += q0 * k0; s[0][1] += q0 * k1; s[0][2] += q0 * k2; s[0][3] += q0 * k3;
            s[1][0] += q1 * k0; s[1][1] += q1 * k1; s[1][2] += q1 * k2; s[1][3] += q1 * k3;
            s[2][0] += q2 * k0; s[2][1] += q2 * k1; s[2][2] += q2 * k2; s[2][3] += q2 * k3;
            s[3][0] += q3 * k0; s[3][1] += q3 * k1; s[3][2] += q3 * k2; s[3][3] += q3 * k3;
        }

#pragma unroll
        for (int i = 0; i < 4; i++) {
            float mx = fmaxf(fmaxf(s[i][0], s[i][1]), fmaxf(s[i][2], s[i][3]));
#pragma unroll
            for (int off = 1; off < 16; off <<= 1)
                mx = fmaxf(mx, __shfl_xor_sync(0xffffffffu, mx, off));
            float mn = fmaxf(mrow[i], mx);
            float corr = __expf(mrow[i] - mn);
            float rs = 0.f;
#pragma unroll
            for (int j = 0; j < 4; j++) {
                s[i][j] = __expf(s[i][j] - mn);
                rs += s[i][j];
            }
#pragma unroll
            for (int off = 1; off < 16; off <<= 1)
                rs += __shfl_xor_sync(0xffffffffu, rs, off);
            lrow[i] = lrow[i] * corr + rs;
            mrow[i] = mn;
#pragma unroll
            for (int jj = 0; jj < 8; jj++) o[i][jj] *= corr;
            *(float4*)&Ps[((ty << 2) + i) * 64 + (tx << 2)] =
                make_float4(s[i][0], s[i][1], s[i][2], s[i][3]);
        }
        __syncthreads();

#pragma unroll 2
        for (int n = 0; n < 64; n++) {
            float4 v0 = *(const float4*)&Vs[n * 128 + (tx << 2)];
            float4 v1 = *(const float4*)&Vs[n * 128 + 64 + (tx << 2)];
#pragma unroll
            for (int i = 0; i < 4; i++) {
                float p = Ps[((ty << 2) + i) * 64 + n];
                o[i][0] += p * v0.x; o[i][1] += p * v0.y;
                o[i][2] += p * v0.z; o[i][3] += p * v0.w;
                o[i][4] += p * v1.x; o[i][5] += p * v1.y;
                o[i][6] += p * v1.z; o[i][7] += p * v1.w;
            }
        }
        __syncthreads();
    }

#pragma unroll
    for (int i = 0; i < 4; i++) {
        float inv = 1.0f / lrow[i];
        size_t base = (size_t)(m0 + (ty << 2) + i) * 2048 + hoff;
        *(float4*)&Og[base + (tx << 2)] =
            make_float4(o[i][0] * inv, o[i][1] * inv, o[i][2] * inv, o[i][3] * inv);
        *(float4*)&Og[base + 64 + (tx << 2)] =
            make_float4(o[i][4] * inv, o[i][5] * inv, o[i][6] * inv, o[i][7] * inv);
    }
}

// ---------------------------------------------------------------------------
// Launch
// ---------------------------------------------------------------------------
extern "C" void kernel_launch(void* const* d_in, const int* in_sizes, int n_in,
                              void* d_out, int out_size) {
    const float* x  = (const float*)d_in[0];
    const float* wq = (const float*)d_in[1];
    const float* wk = (const float*)d_in[2];
    const float* wv = (const float*)d_in[3];
    const float* wo = (const float*)d_in[4];
    const float* qn = (const float*)d_in[5];
    const float* kn = (const float*)d_in[6];
    float* out = (float*)d_out;

    void *pq, *pk, *pv, *pa, *pxh, *pxl, *pwh, *pwl;
    cudaGetSymbolAddress(&pq, g_Q);
    cudaGetSymbolAddress(&pk, g_K);
    cudaGetSymbolAddress(&pv, g_V);
    cudaGetSymbolAddress(&pa, g_A);
    cudaGetSymbolAddress(&pxh, g_Xhi);
    cudaGetSymbolAddress(&pxl, g_Xlo);
    cudaGetSymbolAddress(&pwh, g_Whi);
    cudaGetSymbolAddress(&pwl, g_Wlo);
    float* Q = (float*)pq;
    float* K = (float*)pk;
    float* V = (float*)pv;
    float* A = (float*)pa;
    __nv_bfloat16* Xhi = (__nv_bfloat16*)pxh;
    __nv_bfloat16* Xlo = (__nv_bfloat16*)pxl;
    __nv_bfloat16* Whi = (__nv_bfloat16*)pwh;
    __nv_bfloat16* Wlo = (__nv_bfloat16*)pwl;

    cudaFuncSetAttribute(flash_attn, cudaFuncAttributeMaxDynamicSharedMemorySize, FA_SMEM);
    cudaFuncSetAttribute(gemm_mma, cudaFuncAttributeMaxDynamicSharedMemorySize, GM_SMEM);

    const int M = 4096, D = 2048;
    const int nX4 = M * D / 4;
    const int nW4 = D * D / 4;
    dim3 gg(D / 128, M / 128);   // (16, 32)

    split_bf16<<<(nX4 + 255) / 256, 256>>>(x, Xhi, Xlo, nX4);

    split_bf16<<<(nW4 + 255) / 256, 256>>>(wq, Whi, Wlo, nW4);
    gemm_mma<<<gg, 256, GM_SMEM>>>(Xhi, Xlo, Whi, Wlo, Q, M, D, D);

    split_bf16<<<(nW4 + 255) / 256, 256>>>(wk, Whi, Wlo, nW4);
    gemm_mma<<<gg, 256, GM_SMEM>>>(Xhi, Xlo, Whi, Wlo, K, M, D, D);

    split_bf16<<<(nW4 + 255) / 256, 256>>>(wv, Whi, Wlo, nW4);
    gemm_mma<<<gg, 256, GM_SMEM>>>(Xhi, Xlo, Whi, Wlo, V, M, D, D);

    int nrows = M * 16;
    rmsnorm_rows<<<nrows / 8, 256>>>(Q, qn, nrows);
    rmsnorm_rows<<<nrows / 8, 256>>>(K, kn, nrows);

    flash_attn<<<dim3(M / 64, 16), 256, FA_SMEM>>>(Q, K, V, A);

    split_bf16<<<(nX4 + 255) / 256, 256>>>(A, Xhi, Xlo, nX4);
    split_bf16<<<(nW4 + 255) / 256, 256>>>(wo, Whi, Wlo, nW4);
    gemm_mma<<<gg, 256, GM_SMEM>>>(Xhi, Xlo, Whi, Wlo, out, M, D, D);
}

// round 4
// speedup vs baseline: 2.3381x; 1.9315x over previous
#include <cuda_runtime.h>
#include <cuda_bf16.h>
#include <cstdint>
#include <math.h>

// ---------------- scratch (static device globals; no allocation) ----------
__device__ float g_Q[4096 * 2048];
__device__ float g_K[4096 * 2048];
__device__ float g_V[4096 * 2048];
__device__ float g_A[4096 * 2048];
__device__ __nv_bfloat16 g_Xhi[4096 * 2048];
__device__ __nv_bfloat16 g_Xlo[4096 * 2048];
__device__ __nv_bfloat16 g_Whi[2048 * 2048];
__device__ __nv_bfloat16 g_Wlo[2048 * 2048];
__device__ __nv_bfloat16 g_Qhi[4096 * 2048];
__device__ __nv_bfloat16 g_Qlo[4096 * 2048];
__device__ __nv_bfloat16 g_Khi[4096 * 2048];
__device__ __nv_bfloat16 g_Klo[4096 * 2048];
__device__ __nv_bfloat16 g_VThi[2048 * 4096];   // [h*128+d][s]
__device__ __nv_bfloat16 g_VTlo[2048 * 4096];

// ======================= portable PTX helpers (sm_80+) =====================
__device__ __forceinline__ uint32_t smem_u32(const void* p) {
    uint32_t a;
    asm("{ .reg .u64 t; cvta.to.shared.u64 t, %1; cvt.u32.u64 %0, t; }"
        : "=r"(a) : "l"(p));
    return a;
}
#define CP_ASYNC16(dst, src) \
    asm volatile("cp.async.cg.shared.global [%0], [%1], 16;" \
                 :: "r"(dst), "l"(src))
#define CP_COMMIT() asm volatile("cp.async.commit_group;")
#define CP_WAIT1()  asm volatile("cp.async.wait_group 1;")
#define CP_WAIT0()  asm volatile("cp.async.wait_group 0;")
#define LDSM_X4(r, addr) \
    asm volatile("ldmatrix.sync.aligned.m8n8.x4.shared.b16 {%0,%1,%2,%3}, [%4];" \
                 : "=r"((r)[0]), "=r"((r)[1]), "=r"((r)[2]), "=r"((r)[3]) \
                 : "r"(addr))
#define MMA16816(d, a, b0, b1) \
    asm volatile("mma.sync.aligned.m16n8k16.row.col.f32.bf16.bf16.f32 " \
                 "{%0,%1,%2,%3}, {%4,%5,%6,%7}, {%8,%9}, {%0,%1,%2,%3};" \
                 : "+f"((d)[0]), "+f"((d)[1]), "+f"((d)[2]), "+f"((d)[3]) \
                 : "r"((a)[0]), "r"((a)[1]), "r"((a)[2]), "r"((a)[3]), \
                   "r"(b0), "r"(b1))
__device__ __forceinline__ float ex2(float x) {
    float r;
    asm("ex2.approx.f32 %0, %1;" : "=f"(r) : "f"(x));
    return r;
}

// ---------------------------------------------------------------------------
// split fp32 -> bf16 hi + bf16 lo (optional scale folded in)
// ---------------------------------------------------------------------------
__global__ void __launch_bounds__(256) split_bf16(const float* __restrict__ in,
                                                  __nv_bfloat16* __restrict__ hi,
                                                  __nv_bfloat16* __restrict__ lo,
                                                  int n4, float scale) {
    int i = blockIdx.x * blockDim.x + threadIdx.x;
    if (i >= n4) return;
    float4 v = ((const float4*)in)[i];
    v.x *= scale; v.y *= scale; v.z *= scale; v.w *= scale;
    union { __nv_bfloat16 b[4]; uint2 u; } H, L;
    H.b[0] = __float2bfloat16(v.x);
    H.b[1] = __float2bfloat16(v.y);
    H.b[2] = __float2bfloat16(v.z);
    H.b[3] = __float2bfloat16(v.w);
    L.b[0] = __float2bfloat16(v.x - __bfloat162float(H.b[0]));
    L.b[1] = __float2bfloat16(v.y - __bfloat162float(H.b[1]));
    L.b[2] = __float2bfloat16(v.z - __bfloat162float(H.b[2]));
    L.b[3] = __float2bfloat16(v.w - __bfloat162float(H.b[3]));
    ((uint2*)hi)[i] = H.u;
    ((uint2*)lo)[i] = L.u;
}

// ---------------------------------------------------------------------------
// transpose + split V: in [4096][2048] fp32 -> VT hi/lo [2048][4096] bf16
// 32x32 tiles, block 256 threads.
// ---------------------------------------------------------------------------
__global__ void __launch_bounds__(256) transpose_split(
    const float* __restrict__ in, __nv_bfloat16* __restrict__ thi,
    __nv_bfloat16* __restrict__ tlo) {
    __shared__ float t[32][33];
    const int s0 = blockIdx.x << 5;
    const int c0 = blockIdx.y << 5;
    const int tx = threadIdx.x & 31;
    const int ty = threadIdx.x >> 5;   // 0..7
#pragma unroll
    for (int i = 0; i < 4; i++) {
        int r = (ty << 2) + i;
        t[r][tx] = in[(size_t)(s0 + r) * 2048 + c0 + tx];
    }
    __syncthreads();
#pragma unroll
    for (int i = 0; i < 4; i++) {
        int r = (ty << 2) + i;          // local col (dh)
        float v = t[tx][r];
        __nv_bfloat16 h = __float2bfloat16(v);
        __nv_bfloat16 l = __float2bfloat16(v - __bfloat162float(h));
        size_t o = (size_t)(c0 + r) * 4096 + s0 + tx;
        thi[o] = h;
        tlo[o] = l;
    }
}

// ---------------------------------------------------------------------------
// mma.sync split-bf16 GEMM: C[M,N] = (Ahi+Alo)[M,K] * (Bhi+Blo)[N,K]^T
// (unchanged from round 3)
// ---------------------------------------------------------------------------
#define GM_STAGE 32768
#define GM_SMEM  (2 * GM_STAGE)

__global__ void __launch_bounds__(256, 2) gemm_mma(
    const __nv_bfloat16* __restrict__ Ahi, const __nv_bfloat16* __restrict__ Alo,
    const __nv_bfloat16* __restrict__ Bhi, const __nv_bfloat16* __restrict__ Blo,
    float* __restrict__ C, int M, int N, int K) {
    extern __shared__ char smem[];
    const uint32_t sbase = smem_u32(smem);
    const int tid = threadIdx.x;
    const int lane = tid & 31;
    const int wid = tid >> 5;
    const int m0 = blockIdx.y << 7;
    const int n0 = blockIdx.x << 7;
    const int wm = (wid & 1) << 6;
    const int wn = (wid >> 1) << 5;

    const __nv_bfloat16* PA[3] = {Ahi, Alo, Ahi};
    const __nv_bfloat16* PB[3] = {Bhi, Bhi, Blo};

    float acc[4][4][4];
#pragma unroll
    for (int mi = 0; mi < 4; mi++)
#pragma unroll
        for (int ni = 0; ni < 4; ni++)
#pragma unroll
            for (int q = 0; q < 4; q++) acc[mi][ni][q] = 0.f;

    const int lr = tid >> 1;
    const int lc0 = (tid & 1) << 2;
    const int NITER = 3 * (K >> 6);

#define GM_ISSUE(it, buf) do {                                                 \
    int _p = (it) / (K >> 6);                                                  \
    int _kk = ((it) % (K >> 6)) << 6;                                          \
    const __nv_bfloat16* _Ag = PA[_p] + (size_t)(m0 + lr) * K + _kk;           \
    const __nv_bfloat16* _Bg = PB[_p] + (size_t)(n0 + lr) * K + _kk;           \
    uint32_t _rowA = sbase + (buf) * GM_STAGE + lr * 128;                      \
    uint32_t _rowB = _rowA + 16384;                                            \
    _Pragma("unroll")                                                          \
    for (int _j = 0; _j < 4; _j++) {                                           \
        int _c = lc0 + _j;                                                     \
        uint32_t _sw = (uint32_t)((_c ^ (lr & 7)) << 4);                       \
        CP_ASYNC16(_rowA + _sw, _Ag + _c * 8);                                 \
        CP_ASYNC16(_rowB + _sw, _Bg + _c * 8);                                 \
    }                                                                          \
} while (0)

    GM_ISSUE(0, 0);
    CP_COMMIT();

    for (int it = 0; it < NITER; it++) {
        const int buf = it & 1;
        if (it + 1 < NITER) {
            GM_ISSUE(it + 1, buf ^ 1);
            CP_COMMIT();
            CP_WAIT1();
        } else {
            CP_WAIT0();
        }
        __syncthreads();

        const uint32_t sA = sbase + buf * GM_STAGE;
        const uint32_t sB = sA + 16384;

#pragma unroll
        for (int ks = 0; ks < 4; ks++) {
            uint32_t a[4][4], b[2][4];
#pragma unroll
            for (int mi = 0; mi < 4; mi++) {
                int row = wm + mi * 16 + (lane & 15);
                int kb = ks * 32 + ((lane >> 4) << 4);
                uint32_t addr = sA + row * 128 + (kb ^ ((row & 7) << 4));
                LDSM_X4(a[mi], addr);
            }
#pragma unroll
            for (int pr = 0; pr < 2; pr++) {
                int row = wn + pr * 16 + (lane & 7) + (((lane >> 4) & 1) << 3);
                int kb = ks * 32 + (((lane >> 3) & 1) << 4);
                uint32_t addr = sB + row * 128 + (kb ^ ((row & 7) << 4));
                LDSM_X4(b[pr], addr);
            }
#pragma unroll
            for (int mi = 0; mi < 4; mi++)
#pragma unroll
                for (int ni = 0; ni < 4; ni++) {
                    uint32_t b0 = b[ni >> 1][(ni & 1) << 1];
                    uint32_t b1 = b[ni >> 1][((ni & 1) << 1) + 1];
                    MMA16816(acc[mi][ni], a[mi], b0, b1);
                }
        }
        __syncthreads();
    }

#pragma unroll
    for (int mi = 0; mi < 4; mi++) {
        int r0 = m0 + wm + mi * 16 + (lane >> 2);
#pragma unroll
        for (int ni = 0; ni < 4; ni++) {
            int cc = n0 + wn + ni * 8 + ((lane & 3) << 1);
            float2 v0 = make_float2(acc[mi][ni][0], acc[mi][ni][1]);
            float2 v1 = make_float2(acc[mi][ni][2], acc[mi][ni][3]);
            *(float2*)&C[(size_t)r0 * N + cc] = v0;
            *(float2*)&C[(size_t)(r0 + 8) * N + cc] = v1;
        }
    }
}

// ---------------------------------------------------------------------------
// Per-(token,head) RMSNorm, in place.
// ---------------------------------------------------------------------------
__global__ void __launch_bounds__(256) rmsnorm_rows(float* __restrict__ X,
                                                    const float* __restrict__ w,
                                                    int nrows) {
    int warp = (blockIdx.x * blockDim.x + threadIdx.x) >> 5;
    int lane = threadIdx.x & 31;
    if (warp >= nrows) return;

    float4 v = *(const float4*)&X[(size_t)warp * 128 + (lane << 2)];
    float ss = v.x * v.x + v.y * v.y + v.z * v.z + v.w * v.w;
#pragma unroll
    for (int off = 16; off > 0; off >>= 1)
        ss += __shfl_xor_sync(0xffffffffu, ss, off);

    float inv = rsqrtf(ss * (1.0f / 128.0f) + 1e-6f);
    float4 wv = *(const float4*)&w[lane << 2];
    v.x *= inv * wv.x; v.y *= inv * wv.y;
    v.z *= inv * wv.z; v.w *= inv * wv.w;
    *(float4*)&X[(size_t)warp * 128 + (lane << 2)] = v;
}

// ---------------------------------------------------------------------------
// Flash attention with mma.sync bf16 hi/lo (3-pass). Per CTA: 128 queries of
// one head; 8 warps x 16 rows. K tiles of 64 keys, cp.async double buffer.
// Q scale includes 1/sqrt(128)*log2(e) -> softmax done base-2 (ex2.approx).
// smem: Qhi|Qlo (2x32KB) + 2 stages x (Khi|Klo 16KB each + VThi|VTlo 16KB each)
// ---------------------------------------------------------------------------
#define FM_QHI   0
#define FM_QLO   32768
#define FM_STG0  65536
#define FM_STAGE 65536               // Khi 0 | Klo 16384 | Vhi 32768 | Vlo 49152
#define FM_SMEM  (65536 + 2 * FM_STAGE)   // 196608

__device__ __forceinline__ uint32_t sw256(int row, int kb) {
    return (uint32_t)(row * 256 + ((kb & 0x80) | ((kb ^ ((row & 7) << 4)) & 0x70)));
}

__global__ void __launch_bounds__(256, 1) flash_mma(
    const __nv_bfloat16* __restrict__ Qhi, const __nv_bfloat16* __restrict__ Qlo,
    const __nv_bfloat16* __restrict__ Khi, const __nv_bfloat16* __restrict__ Klo,
    const __nv_bfloat16* __restrict__ VThi, const __nv_bfloat16* __restrict__ VTlo,
    float* __restrict__ Og) {
    extern __shared__ char smem[];
    const uint32_t sb = smem_u32(smem);
    const int tid = threadIdx.x;
    const int lane = tid & 31;
    const int wid = tid >> 5;
    const int h = blockIdx.y;
    const int m0 = blockIdx.x << 7;
    const int hoff = h << 7;
    const int qbase = wid << 4;          // warp's 16 q rows

    // ---- load Q tiles (hi/lo), 16 chunks per thread ----
    {
        int row = tid >> 1;
        int c0 = (tid & 1) << 3;
        const __nv_bfloat16* qh = Qhi + (size_t)(m0 + row) * 2048 + hoff;
        const __nv_bfloat16* ql = Qlo + (size_t)(m0 + row) * 2048 + hoff;
#pragma unroll
        for (int j = 0; j < 8; j++) {
            int c = c0 + j;
            uint32_t sw = sw256(row, c << 4);
            CP_ASYNC16(sb + FM_QHI + sw, qh + c * 8);
            CP_ASYNC16(sb + FM_QLO + sw, ql + c * 8);
        }
    }

    // ---- K/V stage loader ----
    const int krow = tid >> 2;           // 0..63
    const int kc0 = (tid & 3) << 2;      // 4 chunks of 16
    const int vrow = tid >> 1;           // 0..127
    const int vc0 = (tid & 1) << 2;      // 4 chunks of 8

#define FM_ISSUE(kt, buf) do {                                                  \
    uint32_t _st = sb + FM_STG0 + (buf) * FM_STAGE;                             \
    const __nv_bfloat16* _kh = Khi + (size_t)((kt) + krow) * 2048 + hoff;       \
    const __nv_bfloat16* _kl = Klo + (size_t)((kt) + krow) * 2048 + hoff;       \
    _Pragma("unroll")                                                           \
    for (int _j = 0; _j < 4; _j++) {                                            \
        int _c = kc0 + _j;                                                      \
        uint32_t _sw = sw256(krow, _c << 4);                                    \
        CP_ASYNC16(_st + _sw, _kh + _c * 8);                                    \
        CP_ASYNC16(_st + 16384 + _sw, _kl + _c * 8);                            \
    }                                                                           \
    const __nv_bfloat16* _vh = VThi + (size_t)(hoff + vrow) * 4096 + (kt);      \
    const __nv_bfloat16* _vl = VTlo + (size_t)(hoff + vrow) * 4096 + (kt);      \
    _Pragma("unroll")                                                           \
    for (int _j = 0; _j < 4; _j++) {                                            \
        int _c = vc0 + _j;                                                      \
        uint32_t _sw = (uint32_t)(vrow * 128 + ((_c << 4) ^ ((vrow & 7) << 4)));\
        CP_ASYNC16(_st + 32768 + _sw, _vh + _c * 8);                            \
        CP_ASYNC16(_st + 49152 + _sw, _vl + _c * 8);                            \
    }                                                                           \
} while (0)

    FM_ISSUE(0, 0);
    CP_COMMIT();

    // softmax state (2 rows per thread)
    float m0s = -1e30f, m1s = -1e30f, l0 = 0.f, l1 = 0.f;
    float o[16][4];
#pragma unroll
    for (int j = 0; j < 16; j++)
#pragma unroll
        for (int q = 0; q < 4; q++) o[j][q] = 0.f;

    const int NITER = 4096 / 64;
    for (int it = 0; it < NITER; it++) {
        const int buf = it & 1;
        if (it + 1 < NITER) {
            FM_ISSUE((it + 1) << 6, buf ^ 1);
            CP_COMMIT();
            CP_WAIT1();
        } else {
            CP_WAIT0();
        }
        __syncthreads();

        const uint32_t sKh = sb + FM_STG0 + buf * FM_STAGE;
        const uint32_t sKl = sKh + 16384;
        const uint32_t sVh = sKh + 32768;
        const uint32_t sVl = sKh + 49152;

        // ---- S = Q K^T (3-pass hi/lo), S tile 16x64 per warp ----
        float s[8][4];
#pragma unroll
        for (int j = 0; j < 8; j++)
#pragma unroll
            for (int q = 0; q < 4; q++) s[j][q] = 0.f;

#pragma unroll
        for (int ks = 0; ks < 8; ks++) {
            uint32_t ah[4], al[4], bh[4][4], bl[4][4];
            {
                int row = qbase + (lane & 15);
                int kb = ks * 32 + ((lane >> 4) << 4);
                LDSM_X4(ah, sb + FM_QHI + sw256(row, kb));
                LDSM_X4(al, sb + FM_QLO + sw256(row, kb));
            }
#pragma unroll
            for (int pr = 0; pr < 4; pr++) {
                int row = pr * 16 + (lane & 7) + (((lane >> 4) & 1) << 3);
                int kb = ks * 32 + (((lane >> 3) & 1) << 4);
                uint32_t sw = sw256(row, kb);
                LDSM_X4(bh[pr], sKh + sw);
                LDSM_X4(bl[pr], sKl + sw);
            }
#pragma unroll
            for (int j = 0; j < 8; j++) {
                int pr = j >> 1, o2 = (j & 1) << 1;
                MMA16816(s[j], ah, bh[pr][o2], bh[pr][o2 + 1]);
                MMA16816(s[j], ah, bl[pr][o2], bl[pr][o2 + 1]);
                MMA16816(s[j], al, bh[pr][o2], bh[pr][o2 + 1]);
            }
        }

        // ---- online softmax (base-2; scale folded into Q) ----
        float mx0 = -1e30f, mx1 = -1e30f;
#pragma unroll
        for (int j = 0; j < 8; j++) {
            mx0 = fmaxf(mx0, fmaxf(s[j][0], s[j][1]));
            mx1 = fmaxf(mx1, fmaxf(s[j][2], s[j][3]));
        }
        mx0 = fmaxf(mx0, __shfl_xor_sync(0xffffffffu, mx0, 1));
        mx0 = fmaxf(mx0, __shfl_xor_sync(0xffffffffu, mx0, 2));
        mx1 = fmaxf(mx1, __shfl_xor_sync(0xffffffffu, mx1, 1));
        mx1 = fmaxf(mx1, __shfl_xor_sync(0xffffffffu, mx1, 2));
        float mn0 = fmaxf(m0s, mx0), mn1 = fmaxf(m1s, mx1);
        float corr0 = ex2(m0s - mn0), corr1 = ex2(m1s - mn1);
        m0s = mn0; m1s = mn1;

        float sum0 = 0.f, sum1 = 0.f;
        float p[8][4];
#pragma unroll
        for (int j = 0; j < 8; j++) {
            p[j][0] = ex2(s[j][0] - mn0);
            p[j][1] = ex2(s[j][1] - mn0);
            p[j][2] = ex2(s[j][2] - mn1);
            p[j][3] = ex2(s[j][3] - mn1);
            sum0 += p[j][0] + p[j][1];
            sum1 += p[j][2] + p[j][3];
        }
        sum0 += __shfl_xor_sync(0xffffffffu, sum0, 1);
        sum0 += __shfl_xor_sync(0xffffffffu, sum0, 2);
        sum1 += __shfl_xor_sync(0xffffffffu, sum1, 1);
        sum1 += __shfl_xor_sync(0xffffffffu, sum1, 2);
        l0 = l0 * corr0 + sum0;
        l1 = l1 * corr1 + sum1;

        // pack P to bf16 hi/lo A-fragments: ahi[kt][4]
        uint32_t pahi[4][4], palo[4][4];
#pragma unroll
        for (int kt = 0; kt < 4; kt++) {
#pragma unroll
            for (int t = 0; t < 2; t++) {   // ntile 2kt+t
                int j = 2 * kt + t;
#pragma unroll
                for (int half = 0; half < 2; half++) {  // rows r / r+8
                    float f0 = p[j][half * 2], f1 = p[j][half * 2 + 1];
                    __nv_bfloat162 hh = __floats2bfloat162_rn(f0, f1);
                    float r0 = f0 - __low2float(hh);
                    float r1 = f1 - __high2float(hh);
                    __nv_bfloat162 ll = __floats2bfloat162_rn(r0, r1);
                    pahi[kt][t * 2 + half] = *(uint32_t*)&hh;
                    palo[kt][t * 2 + half] = *(uint32_t*)&ll;
                }
            }
        }

        // rescale O
#pragma unroll
        for (int j = 0; j < 16; j++) {
            o[j][0] *= corr0; o[j][1] *= corr0;
            o[j][2] *= corr1; o[j][3] *= corr1;
        }

        // ---- O += P V (3-pass hi/lo) ----
#pragma unroll
        for (int kt = 0; kt < 4; kt++) {
#pragma unroll
            for (int pr = 0; pr < 8; pr++) {
                uint32_t bvh[4], bvl[4];
                int row = pr * 16 + (lane & 7) + (((lane >> 4) & 1) << 3);
                int kb = kt * 32 + (((lane >> 3) & 1) << 4);
                uint32_t sw = (uint32_t)(row * 128 + (kb ^ ((row & 7) << 4)));
                LDSM_X4(bvh, sVh + sw);
                LDSM_X4(bvl, sVl + sw);
#pragma unroll
                for (int t = 0; t < 2; t++) {
                    int j = pr * 2 + t;
                    int o2 = t << 1;
                    MMA16816(o[j], pahi[kt], bvh[o2], bvh[o2 + 1]);
                    MMA16816(o[j], pahi[kt], bvl[o2], bvl[o2 + 1]);
                    MMA16816(o[j], palo[kt], bvh[o2], bvh[o2 + 1]);
                }
            }
        }
        __syncthreads();
    }

    // ---- epilogue ----
    float inv0 = 1.0f / l0, inv1 = 1.0f / l1;
    int r0 = m0 + qbase + (lane >> 2);
#pragma unroll
    for (int j = 0; j < 16; j++) {
        int cc = hoff + j * 8 + ((lane & 3) << 1);
        *(float2*)&Og[(size_t)r0 * 2048 + cc] =
            make_float2(o[j][0] * inv0, o[j][1] * inv0);
        *(float2*)&Og[(size_t)(r0 + 8) * 2048 + cc] =
            make_float2(o[j][2] * inv1, o[j][3] * inv1);
    }
}

// ---------------------------------------------------------------------------
// Launch
// ---------------------------------------------------------------------------
extern "C" void kernel_launch(void* const* d_in, const int* in_sizes, int n_in,
                              void* d_out, int out_size) {
    const float* x  = (const float*)d_in[0];
    const float* wq = (const float*)d_in[1];
    const float* wk = (const float*)d_in[2];
    const float* wv = (const float*)d_in[3];
    const float* wo = (const float*)d_in[4];
    const float* qn = (const float*)d_in[5];
    const float* kn = (const float*)d_in[6];
    float* out = (float*)d_out;

    void *pq, *pk, *pv, *pa, *pxh, *pxl, *pwh, *pwl;
    void *pqh, *pql, *pkh, *pkl, *pvh, *pvl;
    cudaGetSymbolAddress(&pq, g_Q);
    cudaGetSymbolAddress(&pk, g_K);
    cudaGetSymbolAddress(&pv, g_V);
    cudaGetSymbolAddress(&pa, g_A);
    cudaGetSymbolAddress(&pxh, g_Xhi);
    cudaGetSymbolAddress(&pxl, g_Xlo);
    cudaGetSymbolAddress(&pwh, g_Whi);
    cudaGetSymbolAddress(&pwl, g_Wlo);
    cudaGetSymbolAddress(&pqh, g_Qhi);
    cudaGetSymbolAddress(&pql, g_Qlo);
    cudaGetSymbolAddress(&pkh, g_Khi);
    cudaGetSymbolAddress(&pkl, g_Klo);
    cudaGetSymbolAddress(&pvh, g_VThi);
    cudaGetSymbolAddress(&pvl, g_VTlo);
    float* Q = (float*)pq;
    float* K = (float*)pk;
    float* V = (float*)pv;
    float* A = (float*)pa;
    __nv_bfloat16* Xhi = (__nv_bfloat16*)pxh;
    __nv_bfloat16* Xlo = (__nv_bfloat16*)pxl;
    __nv_bfloat16* Whi = (__nv_bfloat16*)pwh;
    __nv_bfloat16* Wlo = (__nv_bfloat16*)pwl;

    cudaFuncSetAttribute(gemm_mma, cudaFuncAttributeMaxDynamicSharedMemorySize, GM_SMEM);
    cudaFuncSetAttribute(flash_mma, cudaFuncAttributeMaxDynamicSharedMemorySize, FM_SMEM);

    const int M = 4096, D = 2048;
    const int nX4 = M * D / 4;
    const int nW4 = D * D / 4;
    dim3 gg(D / 128, M / 128);

    split_bf16<<<(nX4 + 255) / 256, 256>>>(x, Xhi, Xlo, nX4, 1.0f);

    split_bf16<<<(nW4 + 255) / 256, 256>>>(wq, Whi, Wlo, nW4, 1.0f);
    gemm_mma<<<gg, 256, GM_SMEM>>>(Xhi, Xlo, Whi, Wlo, Q, M, D, D);

    split_bf16<<<(nW4 + 255) / 256, 256>>>(wk, Whi, Wlo, nW4, 1.0f);
    gemm_mma<<<gg, 256, GM_SMEM>>>(Xhi, Xlo, Whi, Wlo, K, M, D, D);

    split_bf16<<<(nW4 + 255) / 256, 256>>>(wv, Whi, Wlo, nW4, 1.0f);
    gemm_mma<<<gg, 256, GM_SMEM>>>(Xhi, Xlo, Whi, Wlo, V, M, D, D);

    int nrows = M * 16;
    rmsnorm_rows<<<nrows / 8, 256>>>(Q, qn, nrows);
    rmsnorm_rows<<<nrows / 8, 256>>>(K, kn, nrows);

    // softmax scale * log2(e) folded into Q
    const float qscale = 0.08838834764831845f * 1.4426950408889634f;
    split_bf16<<<(nX4 + 255) / 256, 256>>>(Q, (__nv_bfloat16*)pqh,
                                           (__nv_bfloat16*)pql, nX4, qscale);
    split_bf16<<<(nX4 + 255) / 256, 256>>>(K, (__nv_bfloat16*)pkh,
                                           (__nv_bfloat16*)pkl, nX4, 1.0f);
    transpose_split<<<dim3(M / 32, D / 32), 256>>>(V, (__nv_bfloat16*)pvh,
                                                   (__nv_bfloat16*)pvl);

    flash_mma<<<dim3(M / 128, 16), 256, FM_SMEM>>>(
        (__nv_bfloat16*)pqh, (__nv_bfloat16*)pql,
        (__nv_bfloat16*)pkh, (__nv_bfloat16*)pkl,
        (__nv_bfloat16*)pvh, (__nv_bfloat16*)pvl, A);

    split_bf16<<<(nX4 + 255) / 256, 256>>>(A, Xhi, Xlo, nX4, 1.0f);
    split_bf16<<<(nW4 + 255) / 256, 256>>>(wo, Whi, Wlo, nW4, 1.0f);
    gemm_mma<<<gg, 256, GM_SMEM>>>(Xhi, Xlo, Whi, Wlo, out, M, D, D);
}